// round 13
// baseline (speedup 1.0000x reference)
#include <cuda_runtime.h>
#include <cuda_fp16.h>

#define NMAX   50000
#define EMAX   800000
#define INDIM  128
#define OUTDIM 64
#define CAP    128              // fixed bucket stride (Poisson(16): P(deg>=128)~0)

// Scratch (device globals: allocation-free rule)
__device__ __half2 g_zh[NMAX * 32];              // z in fp16 (32 half2 / row)
__device__ float  g_s[NMAX];                     // src-half attention proj
__device__ float  g_t[NMAX];                     // dst-half attention proj
__device__ __align__(16) int g_cnt[NMAX];        // in-degree counts
__device__ __align__(16) int g_rank[EMAX];       // per-edge rank in dst bucket
__device__ float2 g_edge[NMAX * CAP];            // fixed-stride (src bits, ex)

// ---------------------------------------------------------------------------
// f32x2 helpers (FFMA2 only reachable via PTX fma.rn.f32x2)
__device__ __forceinline__ unsigned long long splat2(float a) {
    unsigned long long r;
    asm("mov.b64 %0, {%1, %1};" : "=l"(r) : "f"(a));
    return r;
}
__device__ __forceinline__ void fma2(unsigned long long& d,
                                     unsigned long long a, unsigned long long b) {
    asm("fma.rn.f32x2 %0, %1, %2, %0;" : "+l"(d) : "l"(a), "l"(b));
}

// ---------------------------------------------------------------------------
// Kernel A (fused): blocks [0, NG) compute z = h @ W (FFMA2, fp16 z store,
//                   s/t folded); blocks [NG, NG+HB) do histogram + rank.
__global__ __launch_bounds__(256) void k_fused(const float* __restrict__ h,
                                               const float* __restrict__ W,
                                               const float* __restrict__ Wa,
                                               const int4* __restrict__ dst4,
                                               int N, int E4, int NG) {
    __shared__ float2 sw2[INDIM * 32];

    if (blockIdx.x >= NG) {
        int t = (blockIdx.x - NG) * 256 + threadIdx.x;
        if (t < E4) {
            int4 d = __ldg(dst4 + t);
            int4 r;
            r.x = atomicAdd(&g_cnt[d.x], 1);
            r.y = atomicAdd(&g_cnt[d.y], 1);
            r.z = atomicAdd(&g_cnt[d.z], 1);
            r.w = atomicAdd(&g_cnt[d.w], 1);
            ((int4*)g_rank)[t] = r;
        }
        return;
    }

    // ---- GEMM half ----
    const int tid  = threadIdx.x;
    const int row0 = blockIdx.x * 64;

    const float2* W2 = (const float2*)W;
    for (int idx = tid; idx < INDIM * 32; idx += 256)
        sw2[idx] = W2[idx];
    __syncthreads();

    const int tx = tid & 15;
    const int ty = tid >> 4;

    int  rows[4];
    bool rv[4];
#pragma unroll
    for (int i = 0; i < 4; i++) { rows[i] = row0 + ty + 16 * i; rv[i] = rows[i] < N; }

    unsigned long long acc2[4][2];
#pragma unroll
    for (int i = 0; i < 4; i++) { acc2[i][0] = 0ull; acc2[i][1] = 0ull; }

    const float4 f4z = make_float4(0.f, 0.f, 0.f, 0.f);

#pragma unroll 4
    for (int k = 0; k < INDIM; k += 4) {
        float4 hv[4];
#pragma unroll
        for (int i = 0; i < 4; i++)
            hv[i] = rv[i] ? __ldg((const float4*)(h + (size_t)rows[i] * INDIM + k)) : f4z;
#pragma unroll
        for (int ks = 0; ks < 4; ks++) {
            unsigned long long w0 = *(const unsigned long long*)&sw2[(k + ks) * 32 + tx];
            unsigned long long w1 = *(const unsigned long long*)&sw2[(k + ks) * 32 + tx + 16];
#pragma unroll
            for (int i = 0; i < 4; i++) {
                const float* hp = &hv[i].x;
                unsigned long long aa = splat2(hp[ks]);
                fma2(acc2[i][0], aa, w0);
                fma2(acc2[i][1], aa, w1);
            }
        }
    }

    float wa_s[2][2], wa_t[2][2];
#pragma unroll
    for (int j = 0; j < 2; j++) {
        int c = (tx + 16 * j) * 2;
        wa_s[j][0] = __ldg(Wa + c);          wa_s[j][1] = __ldg(Wa + c + 1);
        wa_t[j][0] = __ldg(Wa + OUTDIM + c); wa_t[j][1] = __ldg(Wa + OUTDIM + c + 1);
    }

#pragma unroll
    for (int i = 0; i < 4; i++) {
        float2 a0 = *(float2*)&acc2[i][0];
        float2 a1 = *(float2*)&acc2[i][1];
        if (rv[i]) {
            __half2* zr = g_zh + (size_t)rows[i] * 32;
            zr[tx]      = __floats2half2_rn(a0.x, a0.y);
            zr[tx + 16] = __floats2half2_rn(a1.x, a1.y);
        }
        float sp = a0.x * wa_s[0][0] + a0.y * wa_s[0][1]
                 + a1.x * wa_s[1][0] + a1.y * wa_s[1][1];
        float tp = a0.x * wa_t[0][0] + a0.y * wa_t[0][1]
                 + a1.x * wa_t[1][0] + a1.y * wa_t[1][1];
#pragma unroll
        for (int off = 8; off > 0; off >>= 1) {
            sp += __shfl_xor_sync(0xffffffffu, sp, off, 16);
            tp += __shfl_xor_sync(0xffffffffu, tp, off, 16);
        }
        if (tx == 0 && rv[i]) { g_s[rows[i]] = sp; g_t[rows[i]] = tp; }
    }
}

// ---------------------------------------------------------------------------
// K2: bucket fill, atomic-free, NO offsets: pos = dst*CAP + rank.
__global__ __launch_bounds__(256) void k_fill(const int* __restrict__ src,
                                              const int* __restrict__ dst,
                                              int E) {
    int i = blockIdx.x * blockDim.x + threadIdx.x;
    if (i >= E) return;
    int s = src[i];
    int d = dst[i];
    int r = g_rank[i];
    float ex = __expf(fmaxf(__ldg(g_s + s) + __ldg(g_t + d), 0.0f));
    g_edge[(size_t)d * CAP + r] = make_float2(__int_as_float(s), ex);
}

// ---------------------------------------------------------------------------
// K3: one warp per dst node; half-warp split over fp16 z rows (128B = 1 line,
//     16 lanes x uint2). Reads its own count, then zeroes it (single
//     consumer -> race-free) so hist starts from zero on the next replay.
__global__ __launch_bounds__(256) void k_node(float* __restrict__ out, int N) {
    int warp = (blockIdx.x * blockDim.x + threadIdx.x) >> 5;
    int lane = threadIdx.x & 31;
    if (warp >= N) return;

    int deg = g_cnt[warp];              // L1-broadcast across the warp
    if (lane == 0) g_cnt[warp] = 0;     // restore state for next replay

    const float2* ebase = g_edge + (size_t)warp * CAP;
    const int q    = lane & 15;
    const int half = lane >> 4;

    const uint2* zr16 = (const uint2*)g_zh;   // 16 uint2 per z row
    float4 acc = make_float4(0.f, 0.f, 0.f, 0.f);
    float  den = 0.0f;

#pragma unroll 4
    for (int jb = 0; jb < deg; jb += 2) {
        int j = jb + half;
        if (j < deg) {
            float2 pr = __ldg(ebase + j);            // uniform per half-warp
            float  a  = pr.y;
            int    s2 = __float_as_int(pr.x);
            den += a;
            uint2 u = __ldg(zr16 + (size_t)s2 * 16 + q);
            float2 f0 = __half22float2(*(const __half2*)&u.x);
            float2 f1 = __half22float2(*(const __half2*)&u.y);
            acc.x += a * f0.x;
            acc.y += a * f0.y;
            acc.z += a * f1.x;
            acc.w += a * f1.y;
        }
    }

    den   += __shfl_xor_sync(0xffffffffu, den,   16);
    acc.x += __shfl_xor_sync(0xffffffffu, acc.x, 16);
    acc.y += __shfl_xor_sync(0xffffffffu, acc.y, 16);
    acc.z += __shfl_xor_sync(0xffffffffu, acc.z, 16);
    acc.w += __shfl_xor_sync(0xffffffffu, acc.w, 16);

    if (half == 0) {
        float rden = (deg > 0) ? (1.0f / den) : 0.0f;
        float4 o;
        o.x = fmaxf(acc.x * rden, 0.0f);
        o.y = fmaxf(acc.y * rden, 0.0f);
        o.z = fmaxf(acc.z * rden, 0.0f);
        o.w = fmaxf(acc.w * rden, 0.0f);
        *(float4*)(out + (size_t)warp * OUTDIM + q * 4) = o;
    }
}

// ---------------------------------------------------------------------------
extern "C" void kernel_launch(void* const* d_in, const int* in_sizes, int n_in,
                              void* d_out, int out_size) {
    const float* h   = (const float*)d_in[0];
    const float* W   = (const float*)d_in[1];
    const float* Wa  = (const float*)d_in[2];
    const int*   src = (const int*)d_in[3];
    const int*   dst = (const int*)d_in[4];
    float* out = (float*)d_out;

    int N  = in_sizes[0] / INDIM;
    int E  = in_sizes[3];
    int E4 = E >> 2;
    int NG = (N + 63) / 64;
    int HB = (E4 + 255) / 256;

    k_fused<<<NG + HB, 256>>>(h, W, Wa, (const int4*)dst, N, E4, NG);
    k_fill <<<(E + 255) / 256, 256>>>(src, dst, E);
    k_node <<<(N * 32 + 255) / 256, 256>>>(out, N);
}

// round 14
// speedup vs baseline: 1.4690x; 1.4690x over previous
#include <cuda_runtime.h>
#include <cuda_fp16.h>

#define NMAX   50000
#define EMAX   800000
#define INDIM  128
#define OUTDIM 64

// Scratch (device globals: allocation-free rule)
__device__ __half2 g_zh[NMAX * 32];              // z in fp16 (32 half2 / row)
__device__ float  g_s[NMAX];                     // src-half attention proj
__device__ float  g_t[NMAX];                     // dst-half attention proj
__device__ __align__(16) int g_meta[NMAX + 4];   // [0,N): cnt  [N]: allocator
__device__ int2   g_od[NMAX];                    // packed {offset, degree}
__device__ __align__(16) int g_rank[EMAX];       // per-edge rank in dst bucket
__device__ float2 g_edge[EMAX];                  // packed (src bits, ex)

#define G_CNT   (g_meta)
#define G_TOTAL (g_meta + NMAX)

// ---------------------------------------------------------------------------
// f32x2 helpers (FFMA2 only reachable via PTX fma.rn.f32x2)
__device__ __forceinline__ unsigned long long splat2(float a) {
    unsigned long long r;
    asm("mov.b64 %0, {%1, %1};" : "=l"(r) : "f"(a));
    return r;
}
__device__ __forceinline__ void fma2(unsigned long long& d,
                                     unsigned long long a, unsigned long long b) {
    asm("fma.rn.f32x2 %0, %1, %2, %0;" : "+l"(d) : "l"(a), "l"(b));
}

// ---------------------------------------------------------------------------
// Kernel A (fused): blocks [0, NG) compute z = h @ W (FFMA2, fp16 z store,
//                   s/t folded); blocks [NG, NG+HB) do histogram + rank.
//     launch_bounds minctas=5: cap regs at 51 -> 5 CTAs/SM residency.
__global__ __launch_bounds__(256, 5) void k_fused(const float* __restrict__ h,
                                                  const float* __restrict__ W,
                                                  const float* __restrict__ Wa,
                                                  const int4* __restrict__ dst4,
                                                  int N, int E4, int NG) {
    __shared__ float2 sw2[INDIM * 32];

    if (blockIdx.x >= NG) {
        int t = (blockIdx.x - NG) * 256 + threadIdx.x;
        if (t < E4) {
            int4 d = __ldg(dst4 + t);
            int4 r;
            r.x = atomicAdd(&G_CNT[d.x], 1);
            r.y = atomicAdd(&G_CNT[d.y], 1);
            r.z = atomicAdd(&G_CNT[d.z], 1);
            r.w = atomicAdd(&G_CNT[d.w], 1);
            ((int4*)g_rank)[t] = r;
        }
        return;
    }

    // ---- GEMM half ----
    const int tid  = threadIdx.x;
    const int row0 = blockIdx.x * 64;

    const float2* W2 = (const float2*)W;
    for (int idx = tid; idx < INDIM * 32; idx += 256)
        sw2[idx] = W2[idx];
    __syncthreads();

    const int tx = tid & 15;
    const int ty = tid >> 4;

    int  rows[4];
    bool rv[4];
#pragma unroll
    for (int i = 0; i < 4; i++) { rows[i] = row0 + ty + 16 * i; rv[i] = rows[i] < N; }

    unsigned long long acc2[4][2];
#pragma unroll
    for (int i = 0; i < 4; i++) { acc2[i][0] = 0ull; acc2[i][1] = 0ull; }

    const float4 f4z = make_float4(0.f, 0.f, 0.f, 0.f);

#pragma unroll 4
    for (int k = 0; k < INDIM; k += 4) {
        float4 hv[4];
#pragma unroll
        for (int i = 0; i < 4; i++)
            hv[i] = rv[i] ? __ldg((const float4*)(h + (size_t)rows[i] * INDIM + k)) : f4z;
#pragma unroll
        for (int ks = 0; ks < 4; ks++) {
            unsigned long long w0 = *(const unsigned long long*)&sw2[(k + ks) * 32 + tx];
            unsigned long long w1 = *(const unsigned long long*)&sw2[(k + ks) * 32 + tx + 16];
#pragma unroll
            for (int i = 0; i < 4; i++) {
                const float* hp = &hv[i].x;
                unsigned long long aa = splat2(hp[ks]);
                fma2(acc2[i][0], aa, w0);
                fma2(acc2[i][1], aa, w1);
            }
        }
    }

    float wa_s[2][2], wa_t[2][2];
#pragma unroll
    for (int j = 0; j < 2; j++) {
        int c = (tx + 16 * j) * 2;
        wa_s[j][0] = __ldg(Wa + c);          wa_s[j][1] = __ldg(Wa + c + 1);
        wa_t[j][0] = __ldg(Wa + OUTDIM + c); wa_t[j][1] = __ldg(Wa + OUTDIM + c + 1);
    }

#pragma unroll
    for (int i = 0; i < 4; i++) {
        float2 a0 = *(float2*)&acc2[i][0];
        float2 a1 = *(float2*)&acc2[i][1];
        if (rv[i]) {
            __half2* zr = g_zh + (size_t)rows[i] * 32;
            zr[tx]      = __floats2half2_rn(a0.x, a0.y);
            zr[tx + 16] = __floats2half2_rn(a1.x, a1.y);
        }
        float sp = a0.x * wa_s[0][0] + a0.y * wa_s[0][1]
                 + a1.x * wa_s[1][0] + a1.y * wa_s[1][1];
        float tp = a0.x * wa_t[0][0] + a0.y * wa_t[0][1]
                 + a1.x * wa_t[1][0] + a1.y * wa_t[1][1];
#pragma unroll
        for (int off = 8; off > 0; off >>= 1) {
            sp += __shfl_xor_sync(0xffffffffu, sp, off, 16);
            tp += __shfl_xor_sync(0xffffffffu, tp, off, 16);
        }
        if (tx == 0 && rv[i]) { g_s[rows[i]] = sp; g_t[rows[i]] = tp; }
    }
}

// ---------------------------------------------------------------------------
// K2: offsets via int4 + warp-shuffle scan; writes packed {offset, degree}.
__global__ __launch_bounds__(256) void k_alloc(int N) {
    __shared__ int wsum[8];
    __shared__ int cbase;
    const int tid = threadIdx.x;
    int base_i = blockIdx.x * 1024 + tid * 4;

    int4 v = make_int4(0, 0, 0, 0);
    if (base_i + 3 < N) {
        v = *(const int4*)(G_CNT + base_i);
    } else {
        if (base_i + 0 < N) v.x = G_CNT[base_i + 0];
        if (base_i + 1 < N) v.y = G_CNT[base_i + 1];
        if (base_i + 2 < N) v.z = G_CNT[base_i + 2];
    }
    int s = v.x + v.y + v.z + v.w;
    int lane = tid & 31, wid = tid >> 5;
    int inc = s;
#pragma unroll
    for (int o = 1; o < 32; o <<= 1) {
        int n = __shfl_up_sync(0xffffffffu, inc, o);
        if (lane >= o) inc += n;
    }
    if (lane == 31) wsum[wid] = inc;
    __syncthreads();
    if (tid == 0) {
        int run = 0;
#pragma unroll
        for (int k = 0; k < 8; k++) { int x = wsum[k]; wsum[k] = run; run += x; }
        cbase = atomicAdd(G_TOTAL, run);
    }
    __syncthreads();
    int o = cbase + wsum[wid] + inc - s;
    if (base_i + 0 < N) { g_od[base_i + 0] = make_int2(o, v.x); o += v.x; }
    if (base_i + 1 < N) { g_od[base_i + 1] = make_int2(o, v.y); o += v.y; }
    if (base_i + 2 < N) { g_od[base_i + 2] = make_int2(o, v.z); o += v.z; }
    if (base_i + 3 < N) { g_od[base_i + 3] = make_int2(o, v.w); }
}

// ---------------------------------------------------------------------------
// K3: bucket fill, atomic-free: pos = off[dst] + rank (scalar form).
//     Also restores g_meta to zero for the next graph replay.
__global__ __launch_bounds__(256) void k_fill(const int* __restrict__ src,
                                              const int* __restrict__ dst,
                                              int E) {
    int i = blockIdx.x * blockDim.x + threadIdx.x;
    int gthreads = gridDim.x * blockDim.x;
    for (int m = i; m <= NMAX; m += gthreads) g_meta[m] = 0;
    if (i >= E) return;
    int s = src[i];
    int d = dst[i];
    int r = g_rank[i];
    float ex = __expf(fmaxf(__ldg(g_s + s) + __ldg(g_t + d), 0.0f));
    int2 od = __ldg(g_od + d);
    g_edge[od.x + r] = make_float2(__int_as_float(s), ex);
}

// ---------------------------------------------------------------------------
// K4: one warp per dst node; half-warp split over fp16 z rows (128B = 1 line,
//     16 lanes x uint2). Unroll 4 -> up to 4 independent gathers in flight.
__global__ __launch_bounds__(256) void k_node(float* __restrict__ out, int N) {
    int warp = (blockIdx.x * blockDim.x + threadIdx.x) >> 5;
    int lane = threadIdx.x & 31;
    if (warp >= N) return;

    int2 od  = __ldg(g_od + warp);
    int  beg = od.x;
    int  deg = od.y;

    const int q    = lane & 15;
    const int half = lane >> 4;

    const uint2* zr16 = (const uint2*)g_zh;   // 16 uint2 per z row
    float4 acc = make_float4(0.f, 0.f, 0.f, 0.f);
    float  den = 0.0f;

#pragma unroll 4
    for (int jb = 0; jb < deg; jb += 2) {
        int j = jb + half;
        if (j < deg) {
            float2 pr = __ldg(g_edge + beg + j);     // uniform per half-warp
            float  a  = pr.y;
            int    s2 = __float_as_int(pr.x);
            den += a;
            uint2 u = __ldg(zr16 + (size_t)s2 * 16 + q);
            float2 f0 = __half22float2(*(const __half2*)&u.x);
            float2 f1 = __half22float2(*(const __half2*)&u.y);
            acc.x += a * f0.x;
            acc.y += a * f0.y;
            acc.z += a * f1.x;
            acc.w += a * f1.y;
        }
    }

    den   += __shfl_xor_sync(0xffffffffu, den,   16);
    acc.x += __shfl_xor_sync(0xffffffffu, acc.x, 16);
    acc.y += __shfl_xor_sync(0xffffffffu, acc.y, 16);
    acc.z += __shfl_xor_sync(0xffffffffu, acc.z, 16);
    acc.w += __shfl_xor_sync(0xffffffffu, acc.w, 16);

    if (half == 0) {
        float rden = (deg > 0) ? (1.0f / den) : 0.0f;
        float4 o;
        o.x = fmaxf(acc.x * rden, 0.0f);
        o.y = fmaxf(acc.y * rden, 0.0f);
        o.z = fmaxf(acc.z * rden, 0.0f);
        o.w = fmaxf(acc.w * rden, 0.0f);
        *(float4*)(out + (size_t)warp * OUTDIM + q * 4) = o;
    }
}

// ---------------------------------------------------------------------------
extern "C" void kernel_launch(void* const* d_in, const int* in_sizes, int n_in,
                              void* d_out, int out_size) {
    const float* h   = (const float*)d_in[0];
    const float* W   = (const float*)d_in[1];
    const float* Wa  = (const float*)d_in[2];
    const int*   src = (const int*)d_in[3];
    const int*   dst = (const int*)d_in[4];
    float* out = (float*)d_out;

    int N  = in_sizes[0] / INDIM;
    int E  = in_sizes[3];
    int E4 = E >> 2;
    int NG = (N + 63) / 64;
    int HB = (E4 + 255) / 256;
    int NB = (N + 1023) >> 10;

    k_fused<<<NG + HB, 256>>>(h, W, Wa, (const int4*)dst, N, E4, NG);
    k_alloc<<<NB, 256>>>(N);
    k_fill <<<(E + 255) / 256, 256>>>(src, dst, E);
    k_node <<<(N * 32 + 255) / 256, 256>>>(out, N);
}

// round 15
// speedup vs baseline: 1.5332x; 1.0437x over previous
#include <cuda_runtime.h>
#include <cuda_fp16.h>

#define NMAX   50000
#define EMAX   800000
#define INDIM  128
#define OUTDIM 64

// Scratch (device globals: allocation-free rule)
__device__ __half2 g_zh[NMAX * 32];              // z in fp16 (32 half2 / row)
__device__ float  g_s[NMAX];                     // src-half attention proj
__device__ float  g_t[NMAX];                     // dst-half attention proj
__device__ __align__(16) int g_meta[NMAX + 4];   // [0,N): cnt  [N]: allocator
__device__ int2   g_od[NMAX];                    // packed {offset, degree}
__device__ __align__(16) int g_rank[EMAX];       // per-edge rank in dst bucket
__device__ float2 g_edge[EMAX];                  // packed (src bits, ex)

#define G_CNT   (g_meta)
#define G_TOTAL (g_meta + NMAX)

// ---------------------------------------------------------------------------
// f32x2 helpers (FFMA2 only reachable via PTX fma.rn.f32x2)
__device__ __forceinline__ unsigned long long splat2(float a) {
    unsigned long long r;
    asm("mov.b64 %0, {%1, %1};" : "=l"(r) : "f"(a));
    return r;
}
__device__ __forceinline__ void fma2(unsigned long long& d,
                                     unsigned long long a, unsigned long long b) {
    asm("fma.rn.f32x2 %0, %1, %2, %0;" : "+l"(d) : "l"(a), "l"(b));
}

// ---------------------------------------------------------------------------
// Kernel A (fused): blocks [0, NG) compute z = h @ W (FFMA2, fp16 z store,
//                   s/t folded); blocks [NG, NG+HB) do histogram + rank.
__global__ __launch_bounds__(256) void k_fused(const float* __restrict__ h,
                                               const float* __restrict__ W,
                                               const float* __restrict__ Wa,
                                               const int4* __restrict__ dst4,
                                               int N, int E4, int NG) {
    __shared__ float2 sw2[INDIM * 32];

    if (blockIdx.x >= NG) {
        int t = (blockIdx.x - NG) * 256 + threadIdx.x;
        if (t < E4) {
            int4 d = __ldg(dst4 + t);
            int4 r;
            r.x = atomicAdd(&G_CNT[d.x], 1);
            r.y = atomicAdd(&G_CNT[d.y], 1);
            r.z = atomicAdd(&G_CNT[d.z], 1);
            r.w = atomicAdd(&G_CNT[d.w], 1);
            ((int4*)g_rank)[t] = r;
        }
        return;
    }

    // ---- GEMM half ----
    const int tid  = threadIdx.x;
    const int row0 = blockIdx.x * 64;

    const float2* W2 = (const float2*)W;
    for (int idx = tid; idx < INDIM * 32; idx += 256)
        sw2[idx] = W2[idx];
    __syncthreads();

    const int tx = tid & 15;
    const int ty = tid >> 4;

    int  rows[4];
    bool rv[4];
#pragma unroll
    for (int i = 0; i < 4; i++) { rows[i] = row0 + ty + 16 * i; rv[i] = rows[i] < N; }

    unsigned long long acc2[4][2];
#pragma unroll
    for (int i = 0; i < 4; i++) { acc2[i][0] = 0ull; acc2[i][1] = 0ull; }

    const float4 f4z = make_float4(0.f, 0.f, 0.f, 0.f);

#pragma unroll 4
    for (int k = 0; k < INDIM; k += 4) {
        float4 hv[4];
#pragma unroll
        for (int i = 0; i < 4; i++)
            hv[i] = rv[i] ? __ldg((const float4*)(h + (size_t)rows[i] * INDIM + k)) : f4z;
#pragma unroll
        for (int ks = 0; ks < 4; ks++) {
            unsigned long long w0 = *(const unsigned long long*)&sw2[(k + ks) * 32 + tx];
            unsigned long long w1 = *(const unsigned long long*)&sw2[(k + ks) * 32 + tx + 16];
#pragma unroll
            for (int i = 0; i < 4; i++) {
                const float* hp = &hv[i].x;
                unsigned long long aa = splat2(hp[ks]);
                fma2(acc2[i][0], aa, w0);
                fma2(acc2[i][1], aa, w1);
            }
        }
    }

    float wa_s[2][2], wa_t[2][2];
#pragma unroll
    for (int j = 0; j < 2; j++) {
        int c = (tx + 16 * j) * 2;
        wa_s[j][0] = __ldg(Wa + c);          wa_s[j][1] = __ldg(Wa + c + 1);
        wa_t[j][0] = __ldg(Wa + OUTDIM + c); wa_t[j][1] = __ldg(Wa + OUTDIM + c + 1);
    }

#pragma unroll
    for (int i = 0; i < 4; i++) {
        float2 a0 = *(float2*)&acc2[i][0];
        float2 a1 = *(float2*)&acc2[i][1];
        if (rv[i]) {
            __half2* zr = g_zh + (size_t)rows[i] * 32;
            zr[tx]      = __floats2half2_rn(a0.x, a0.y);
            zr[tx + 16] = __floats2half2_rn(a1.x, a1.y);
        }
        float sp = a0.x * wa_s[0][0] + a0.y * wa_s[0][1]
                 + a1.x * wa_s[1][0] + a1.y * wa_s[1][1];
        float tp = a0.x * wa_t[0][0] + a0.y * wa_t[0][1]
                 + a1.x * wa_t[1][0] + a1.y * wa_t[1][1];
#pragma unroll
        for (int off = 8; off > 0; off >>= 1) {
            sp += __shfl_xor_sync(0xffffffffu, sp, off, 16);
            tp += __shfl_xor_sync(0xffffffffu, tp, off, 16);
        }
        if (tx == 0 && rv[i]) { g_s[rows[i]] = sp; g_t[rows[i]] = tp; }
    }
}

// ---------------------------------------------------------------------------
// K2: offsets via int4 + warp-shuffle scan; writes packed {offset, degree}.
__global__ __launch_bounds__(256) void k_alloc(int N) {
    __shared__ int wsum[8];
    __shared__ int cbase;
    const int tid = threadIdx.x;
    int base_i = blockIdx.x * 1024 + tid * 4;

    int4 v = make_int4(0, 0, 0, 0);
    if (base_i + 3 < N) {
        v = *(const int4*)(G_CNT + base_i);
    } else {
        if (base_i + 0 < N) v.x = G_CNT[base_i + 0];
        if (base_i + 1 < N) v.y = G_CNT[base_i + 1];
        if (base_i + 2 < N) v.z = G_CNT[base_i + 2];
    }
    int s = v.x + v.y + v.z + v.w;
    int lane = tid & 31, wid = tid >> 5;
    int inc = s;
#pragma unroll
    for (int o = 1; o < 32; o <<= 1) {
        int n = __shfl_up_sync(0xffffffffu, inc, o);
        if (lane >= o) inc += n;
    }
    if (lane == 31) wsum[wid] = inc;
    __syncthreads();
    if (tid == 0) {
        int run = 0;
#pragma unroll
        for (int k = 0; k < 8; k++) { int x = wsum[k]; wsum[k] = run; run += x; }
        cbase = atomicAdd(G_TOTAL, run);
    }
    __syncthreads();
    int o = cbase + wsum[wid] + inc - s;
    if (base_i + 0 < N) { g_od[base_i + 0] = make_int2(o, v.x); o += v.x; }
    if (base_i + 1 < N) { g_od[base_i + 1] = make_int2(o, v.y); o += v.y; }
    if (base_i + 2 < N) { g_od[base_i + 2] = make_int2(o, v.z); o += v.z; }
    if (base_i + 3 < N) { g_od[base_i + 3] = make_int2(o, v.w); }
}

// ---------------------------------------------------------------------------
// K3: bucket fill, atomic-free: pos = off[dst] + rank (scalar form).
//     Also restores g_meta to zero for the next graph replay.
__global__ __launch_bounds__(256) void k_fill(const int* __restrict__ src,
                                              const int* __restrict__ dst,
                                              int E) {
    int i = blockIdx.x * blockDim.x + threadIdx.x;
    int gthreads = gridDim.x * blockDim.x;
    for (int m = i; m <= NMAX; m += gthreads) g_meta[m] = 0;
    if (i >= E) return;
    int s = src[i];
    int d = dst[i];
    int r = g_rank[i];
    float ex = __expf(fmaxf(__ldg(g_s + s) + __ldg(g_t + d), 0.0f));
    int2 od = __ldg(g_od + d);
    g_edge[od.x + r] = make_float2(__int_as_float(s), ex);
}

// ---------------------------------------------------------------------------
// K4: TWO nodes per warp — each 16-lane half owns a full node. Per edge the
//     half loads one uniform (src, ex) pair + the full 128B fp16 z row
//     (16 lanes x uint2). den is identical across the half's lanes and each
//     lane owns its output quad -> NO reduction shuffles, full-warp epilogue.
__global__ __launch_bounds__(256) void k_node(float* __restrict__ out, int N) {
    int lane = threadIdx.x & 31;
    int half = lane >> 4;
    int node = ((blockIdx.x * blockDim.x + threadIdx.x) >> 5) * 2 + half;
    if (node >= N) return;

    int2 od  = __ldg(g_od + node);
    int  beg = od.x;
    int  deg = od.y;

    const int q = lane & 15;
    const uint2* zr16 = (const uint2*)g_zh;   // 16 uint2 per z row
    float4 acc = make_float4(0.f, 0.f, 0.f, 0.f);
    float  den = 0.0f;

#pragma unroll 2
    for (int j = 0; j < deg; j++) {
        float2 pr = __ldg(g_edge + beg + j);         // uniform per half-warp
        float  a  = pr.y;
        int    s2 = __float_as_int(pr.x);
        den += a;
        uint2 u = __ldg(zr16 + (size_t)s2 * 16 + q);
        float2 f0 = __half22float2(*(const __half2*)&u.x);
        float2 f1 = __half22float2(*(const __half2*)&u.y);
        acc.x += a * f0.x;
        acc.y += a * f0.y;
        acc.z += a * f1.x;
        acc.w += a * f1.y;
    }

    float rden = (deg > 0) ? (1.0f / den) : 0.0f;
    float4 o;
    o.x = fmaxf(acc.x * rden, 0.0f);
    o.y = fmaxf(acc.y * rden, 0.0f);
    o.z = fmaxf(acc.z * rden, 0.0f);
    o.w = fmaxf(acc.w * rden, 0.0f);
    *(float4*)(out + (size_t)node * OUTDIM + q * 4) = o;
}

// ---------------------------------------------------------------------------
extern "C" void kernel_launch(void* const* d_in, const int* in_sizes, int n_in,
                              void* d_out, int out_size) {
    const float* h   = (const float*)d_in[0];
    const float* W   = (const float*)d_in[1];
    const float* Wa  = (const float*)d_in[2];
    const int*   src = (const int*)d_in[3];
    const int*   dst = (const int*)d_in[4];
    float* out = (float*)d_out;

    int N  = in_sizes[0] / INDIM;
    int E  = in_sizes[3];
    int E4 = E >> 2;
    int NG = (N + 63) / 64;
    int HB = (E4 + 255) / 256;
    int NB = (N + 1023) >> 10;

    k_fused<<<NG + HB, 256>>>(h, W, Wa, (const int4*)dst, N, E4, NG);
    k_alloc<<<NB, 256>>>(N);
    k_fill <<<(E + 255) / 256, 256>>>(src, dst, E);
    // 2 nodes per warp -> 16 nodes per 256-thread block
    k_node <<<(N + 15) / 16, 256>>>(out, N);
}